// round 7
// baseline (speedup 1.0000x reference)
#include <cuda_runtime.h>
#include <math.h>

// ---------------------------------------------------------------------------
// NUFFT type-2:  image(8,256,256) -> kdata(2,8,131072)
//   1) de-apodization (table) folded into pass1
//   2) centered zero-pad 512x512 fft2 == FFT512(zero-pad) * i^{k1} * i^{k2}
//      FFT512 = 3 register-resident radix-8 rounds, 64 thr/row, XOR-swizzled
//   3) KB 6x6 gather: points binned into 64x64 tiles; weights via smem
//      lerp-LUT; scatter overlapped with FFT passes on a forked stream
// ---------------------------------------------------------------------------

#define IMN   256
#define G     512
#define B_    8
#define M_    131072            // 2^17
#define NPTS  (B_ * M_)         // 1,048,576
#define J_    6
#define NBIN  512               // 8 batches * 8 * 8 tiles
#define TILE  64
#define TROWS 69                // TILE + 5 halo
#define TPITCH 71               // padded pitch (float2 units)
#define CAP   4096              // per-bin capacity (mean 2048)
#define SPLIT 2                 // gather blocks per bin

#define LUTQ  256               // KB LUT resolution (fr in [0,1))
#define LUTP  9                 // LUT pitch (taps padded 6->9, bank-friendly)
#define LUTN  ((LUTQ + 1) * LUTP)

#define HB    256               // scatter blocks
#define HT    512               // scatter threads/block
#define PPB   (NPTS / HB)       // 4096 points per block

#define TILE_F2   (TROWS * TPITCH)
#define GATHER_SMEM ((TILE_F2 + LUTN) * (int)sizeof(float2))

// Scratch (device globals: allocation-free per harness rules)
__device__ float2 g_F2T[B_ * G * IMN];               // pass1 out [b][k2][n1]
__device__ __align__(16) float2 g_KGT[B_ * G * G];   // k-grid    [b][k2][k1]
__device__ float4 g_sorted[NBIN * CAP];              // binned points (32 MB)
__device__ int    g_cnt[NBIN];                       // cursor -> final count
__device__ float2 g_tw[512];                         // exp(-i pi pos/half) at [half+pos]
__device__ float  g_apod[IMN];
__device__ float2 g_kblut[LUTN];                     // (value, slope) per (q, tap)

__device__ __forceinline__ float beta_f() {
    return (float)(3.141592653589793 * sqrt(19.45));  // Beatty beta, OS=2, J=6
}

// Abramowitz & Stegun I0 (rel err ~2e-7) — init-time only
__device__ __forceinline__ float bessi0f(float z) {
    if (z < 3.75f) {
        float t = z * z * (1.0f / 14.0625f);
        return 1.0f + t * (3.5156229f + t * (3.0899424f + t * (1.2067492f +
                     t * (0.2659732f + t * (0.0360768f + t * 0.0045813f)))));
    } else {
        float w = 3.75f / z;
        float p = 0.39894228f + w * (0.01328592f + w * (0.00225319f + w * (-0.00157565f +
                  w * (0.00916281f + w * (-0.02057706f + w * (0.02635537f +
                  w * (-0.01647633f + w * 0.00392377f)))))));
        return p * __expf(z) * rsqrtf(z);
    }
}

__device__ __forceinline__ float kb(float u) {
    float x = u * (1.0f / 3.0f);
    float t = 1.0f - x * x;
    if (t <= 0.0f) return 0.0f;
    return bessi0f(beta_f() * sqrtf(t));
}

__device__ __forceinline__ float2 mul_ik(float2 v, int k) {
    switch (k & 3) {
        case 0:  return v;
        case 1:  return make_float2(-v.y,  v.x);
        case 2:  return make_float2(-v.x, -v.y);
        default: return make_float2( v.y, -v.x);
    }
}

// ---------------------------------------------------------------------------
// complex helpers
__device__ __forceinline__ float2 cmul(float2 a, float2 b) {
    return make_float2(a.x * b.x - a.y * b.y, a.x * b.y + a.y * b.x);
}
__device__ __forceinline__ float2 cadd(float2 a, float2 b) { return make_float2(a.x + b.x, a.y + b.y); }
__device__ __forceinline__ float2 csub(float2 a, float2 b) { return make_float2(a.x - b.x, a.y - b.y); }
__device__ __forceinline__ float2 mulmi(float2 a) { return make_float2(a.y, -a.x); }

__device__ __forceinline__ void bf(float2& u, float2& v, float2 w) {
    float2 t = cmul(w, v);
    v = csub(u, t);
    u = cadd(u, t);
}

__device__ __forceinline__ void bfly8(float2* a, float2 wA, float2 wB, float2 wC) {
    const float S = 0.70710678118654752f;
    bf(a[0], a[1], wA); bf(a[2], a[3], wA); bf(a[4], a[5], wA); bf(a[6], a[7], wA);
    float2 wBm = mulmi(wB);
    bf(a[0], a[2], wB);  bf(a[1], a[3], wBm);
    bf(a[4], a[6], wB);  bf(a[5], a[7], wBm);
    float2 wC1 = cmul(wC, make_float2(S, -S));
    float2 wC2 = mulmi(wC);
    float2 wC3 = cmul(wC, make_float2(-S, -S));
    bf(a[0], a[4], wC);  bf(a[1], a[5], wC1);
    bf(a[2], a[6], wC2); bf(a[3], a[7], wC3);
}

__device__ __forceinline__ int swz(int i) { return i ^ (i >> 3); }

// ---------------------------------------------------------------------------
// Init: twiddle table, apod table, KB LUT, zero bin counters.
__global__ void init_kernel() {
    int i = threadIdx.x;          // 512 threads
    if (i >= 1) {
        int half = 1 << (31 - __clz(i));
        int pos  = i - half;
        float ang = -3.14159265358979f * (float)pos / (float)half;
        float s, c;
        __sincosf(ang, &s, &c);
        g_tw[i] = make_float2(c, s);
    } else {
        g_tw[0] = make_float2(1.0f, 0.0f);
    }
    if (i < IMN) {
        float x   = (float)i - 128.0f;
        float arg = (float)(3.141592653589793) * 6.0f * x / 512.0f;
        float bb  = beta_f();
        float t   = bb * bb - arg * arg;
        float st  = sqrtf(t);
        g_apod[i] = st / sinhf(st);
    }
    g_cnt[i] = 0;
    for (int e = i; e < LUTN; e += 512) {
        int q = e / LUTP, j = e - q * LUTP;
        float v = 0.0f, d = 0.0f;
        if (j < J_) {
            float fr  = (float)q * (1.0f / LUTQ);
            float frn = (float)(q + 1) * (1.0f / LUTQ);
            v = kb(fr  - (float)(j - 2));
            d = kb(frn - (float)(j - 2)) - v;
        }
        g_kblut[e] = make_float2(v, d);
    }
}

// rounds 2+3 shared by both passes
__device__ __forceinline__ void fft_rounds23(float2* a, float2* sh, int t) {
    #pragma unroll
    for (int j = 0; j < 8; j++) sh[swz(8 * t + j)] = a[j];
    __syncthreads();
    int base2 = ((t >> 3) << 6) | (t & 7);
    #pragma unroll
    for (int j = 0; j < 8; j++) a[j] = sh[swz(base2 + 8 * j)];
    {
        int d = t & 7;
        bfly8(a, g_tw[8 + d], g_tw[16 + d], g_tw[32 + d]);
    }
    #pragma unroll
    for (int j = 0; j < 8; j++) sh[swz(base2 + 8 * j)] = a[j];
    __syncthreads();
    #pragma unroll
    for (int j = 0; j < 8; j++) a[j] = sh[swz(t + 64 * j)];
    bfly8(a, g_tw[64 + t], g_tw[128 + t], g_tw[256 + t]);
}

__global__ void __launch_bounds__(64) pass1_kernel(const float* __restrict__ img) {
    int b  = blockIdx.x >> 8;
    int n1 = blockIdx.x & 255;
    int t  = threadIdx.x;
    __shared__ float2 sh[512];

    float a1 = g_apod[n1];
    const float* row = img + ((size_t)b * IMN + n1) * IMN;
    int r6 = __brev((unsigned)t) >> 26;

    float2 a[8];
    const int rev3e[4] = {0, 2, 1, 3};
    #pragma unroll
    for (int e = 0; e < 4; e++) {
        int src = (rev3e[e] << 6) | r6;
        float v = row[src] * g_apod[src] * a1;
        a[2 * e]     = make_float2(v, 0.0f);
        a[2 * e + 1] = make_float2(0.0f, 0.0f);
    }
    bfly8(a, make_float2(1.f, 0.f), make_float2(1.f, 0.f), make_float2(1.f, 0.f));
    fft_rounds23(a, sh, t);

    #pragma unroll
    for (int j = 0; j < 8; j++) {
        int k = t + 64 * j;
        g_F2T[((size_t)b * G + k) * IMN + n1] = mul_ik(a[j], k);
    }
}

__global__ void __launch_bounds__(64) pass2_kernel() {
    int b  = blockIdx.x >> 9;
    int k2 = blockIdx.x & 511;
    int t  = threadIdx.x;
    __shared__ float2 sh[512];

    const float2* src = g_F2T + ((size_t)b * G + k2) * IMN;
    int r6 = __brev((unsigned)t) >> 26;

    float2 a[8];
    const int rev3e[4] = {0, 2, 1, 3};
    #pragma unroll
    for (int e = 0; e < 4; e++) {
        int s = (rev3e[e] << 6) | r6;
        a[2 * e]     = src[s];
        a[2 * e + 1] = make_float2(0.0f, 0.0f);
    }
    bfly8(a, make_float2(1.f, 0.f), make_float2(1.f, 0.f), make_float2(1.f, 0.f));
    fft_rounds23(a, sh, t);

    float2* dst = g_KGT + ((size_t)b * G + k2) * G;
    #pragma unroll
    for (int j = 0; j < 8; j++) {
        int k = t + 64 * j;
        dst[k] = mul_ik(a[j], k);
    }
}

// ---------------------------------------------------------------------------
__device__ __forceinline__ int point_bin(int b, float tm1, float tm2) {
    int w1 = ((int)floorf(tm1)) & 511;
    int w2 = ((int)floorf(tm2)) & 511;
    return (b << 6) | ((w2 >> 6) << 3) | (w1 >> 6);
}

__device__ __forceinline__ void load_point(const float* ktraj, int idx,
                                           float& tm1, float& tm2, int& b) {
    b = idx >> 17;
    int m = idx & (M_ - 1);
    const float SC = (float)(512.0 / (2.0 * 3.141592653589793));
    tm1 = ktraj[((size_t)b * 2)     * M_ + m] * SC;
    tm2 = ktraj[((size_t)b * 2 + 1) * M_ + m] * SC;
}

__global__ void __launch_bounds__(HT) scatter_kernel(const float* __restrict__ ktraj,
                                                     const float* __restrict__ dcf) {
    __shared__ int sh[NBIN];
    int tid = threadIdx.x;
    if (tid < NBIN) sh[tid] = 0;
    __syncthreads();

    int start = blockIdx.x * PPB;

    #pragma unroll 4
    for (int k = tid; k < PPB; k += HT) {
        float tm1, tm2; int b;
        load_point(ktraj, start + k, tm1, tm2, b);
        atomicAdd(&sh[point_bin(b, tm1, tm2)], 1);
    }
    __syncthreads();

    if (tid < NBIN) {
        int v = sh[tid];
        sh[tid] = v ? atomicAdd(&g_cnt[tid], v) : 0;
    }
    __syncthreads();

    #pragma unroll 4
    for (int k = tid; k < PPB; k += HT) {
        int idx = start + k;
        float tm1, tm2; int b;
        load_point(ktraj, idx, tm1, tm2, b);
        int m = idx & (M_ - 1);
        float d = dcf[(size_t)b * M_ + m];
        int bin = point_bin(b, tm1, tm2);
        int pos = atomicAdd(&sh[bin], 1);
        if (pos < CAP)
            g_sorted[(size_t)bin * CAP + pos] = make_float4(tm1, tm2, d, __int_as_float(idx));
    }
}

// ---------------------------------------------------------------------------
// Gather: SPLIT blocks per bin; smem tile + smem KB lerp-LUT.
__global__ void __launch_bounds__(256) gather_bin_kernel(float* __restrict__ out) {
    extern __shared__ float2 dyn[];
    float2* tile = dyn;                 // TILE_F2
    float2* klut = dyn + TILE_F2;       // LUTN

    int bin  = blockIdx.x / SPLIT;
    int part = blockIdx.x - bin * SPLIT;
    int b   = bin >> 6;
    int t2  = (bin >> 3) & 7;
    int t1  = bin & 7;
    int tid = threadIdx.x;

    int r0 = t2 * TILE - 2;
    int c0 = t1 * TILE - 2;

    const float2* base = g_KGT + (size_t)b * G * G;
    for (int i = tid; i < TROWS * TROWS; i += 256) {
        int lr = i / TROWS;
        int lc = i - lr * TROWS;
        int gr = (r0 + lr) & 511;
        int gc = (c0 + lc) & 511;
        tile[lr * TPITCH + lc] = base[(size_t)gr * G + gc];
    }
    for (int i = tid; i < LUTN; i += 256) klut[i] = g_kblut[i];
    __syncthreads();

    int cnt = g_cnt[bin];
    if (cnt > CAP) cnt = CAP;
    int chunk = (cnt + SPLIT - 1) / SPLIT;
    int pbeg  = part * chunk;
    int pend  = pbeg + chunk;
    if (pend > cnt) pend = cnt;
    size_t beg = (size_t)bin * CAP;

    for (int p = pbeg + tid; p < pend; p += 256) {
        float4 pt = g_sorted[beg + p];
        float tm1 = pt.x, tm2 = pt.y, d = pt.z;
        int idx = __float_as_int(pt.w);

        float f1 = floorf(tm1), f2 = floorf(tm2);
        float fr1 = tm1 - f1,   fr2 = tm2 - f2;
        int w1 = ((int)f1) & 511;
        int w2 = ((int)f2) & 511;
        int lc = (w1 & 63) + 2;
        int lr = (w2 & 63) + 2;

        float x1 = fr1 * (float)LUTQ;
        float x2 = fr2 * (float)LUTQ;
        int   q1 = (int)x1;  float fc1 = x1 - (float)q1;
        int   q2 = (int)x2;  float fc2 = x2 - (float)q2;
        const float2* l1 = klut + q1 * LUTP;
        const float2* l2 = klut + q2 * LUTP;

        float a1[J_], a2[J_];
        #pragma unroll
        for (int j = 0; j < J_; j++) {
            float2 e1 = l1[j];
            float2 e2 = l2[j];
            a1[j] = fmaf(fc1, e1.y, e1.x);
            a2[j] = fmaf(fc2, e2.y, e2.x);
        }

        float sre = 0.0f, sim = 0.0f;
        const float2* tp = tile + (lr - 2) * TPITCH + (lc - 2);
        #pragma unroll
        for (int j2 = 0; j2 < J_; j2++) {
            const float2* row = tp + j2 * TPITCH;
            float rre = 0.0f, rim = 0.0f;
            #pragma unroll
            for (int j1 = 0; j1 < J_; j1++) {
                float2 v = row[j1];
                rre = fmaf(a1[j1], v.x, rre);
                rim = fmaf(a1[j1], v.y, rim);
            }
            sre = fmaf(a2[j2], rre, sre);
            sim = fmaf(a2[j2], rim, sim);
        }

        out[idx]           = sre * d;
        out[B_ * M_ + idx] = sim * d;
    }
}

// ---------------------------------------------------------------------------
extern "C" void kernel_launch(void* const* d_in, const int* in_sizes, int n_in,
                              void* d_out, int out_size) {
    const float* image = (const float*)d_in[0];   // (8,256,256)
    const float* ktraj = (const float*)d_in[1];   // (8,2,131072)
    const float* dcf   = (const float*)d_in[2];   // (8,131072)
    float* out = (float*)d_out;                   // (2,8,131072)

    cudaFuncSetAttribute(gather_bin_kernel,
                         cudaFuncAttributeMaxDynamicSharedMemorySize, GATHER_SMEM);

    // fork/join: scatter runs concurrently with the FFT passes
    cudaStream_t side;
    cudaEvent_t efork, ejoin;
    cudaStreamCreateWithFlags(&side, cudaStreamNonBlocking);
    cudaEventCreateWithFlags(&efork, cudaEventDisableTiming);
    cudaEventCreateWithFlags(&ejoin, cudaEventDisableTiming);

    init_kernel<<<1, 512>>>();
    cudaEventRecord(efork, 0);
    cudaStreamWaitEvent(side, efork, 0);

    scatter_kernel<<<HB, HT, 0, side>>>(ktraj, dcf);   // forked
    pass1_kernel  <<<B_ * IMN, 64>>>(image);           // main
    pass2_kernel  <<<B_ * G,   64>>>();                // main

    cudaEventRecord(ejoin, side);
    cudaStreamWaitEvent(0, ejoin, 0);

    gather_bin_kernel<<<NBIN * SPLIT, 256, GATHER_SMEM>>>(out);
}

// round 9
// speedup vs baseline: 1.2362x; 1.2362x over previous
#include <cuda_runtime.h>
#include <math.h>

// ---------------------------------------------------------------------------
// NUFFT type-2:  image(8,256,256) -> kdata(2,8,131072)
//   1) de-apodization (table) folded into pass1
//   2) centered zero-pad 512x512 fft2 == FFT512(zero-pad) * i^{k1} * i^{k2}
//      FFT512 = 3 register-resident radix-8 rounds, 64 thr/row, XOR-swizzled
//   3) KB 6x6 gather: points binned into 64x64 tiles; weights via smem
//      lerp-LUT (LUTQ=128, smem 48.4KB -> 4 blocks/SM)
// ---------------------------------------------------------------------------

#define IMN   256
#define G     512
#define B_    8
#define M_    131072            // 2^17
#define NPTS  (B_ * M_)         // 1,048,576
#define J_    6
#define NBIN  512               // 8 batches * 8 * 8 tiles
#define TILE  64
#define TROWS 69                // TILE + 5 halo
#define TPITCH 71               // padded pitch (float2 units)
#define CAP   4096              // per-bin capacity (mean 2048)
#define SPLIT 2                 // gather blocks per bin

#define LUTQ  128               // KB LUT resolution (fr in [0,1))
#define LUTP  9                 // LUT pitch (taps padded 6->9)
#define LUTN  ((LUTQ + 1) * LUTP)

#define HB    256               // scatter blocks
#define HT    512               // scatter threads/block
#define PPB   (NPTS / HB)       // 4096 points per block

#define TILE_F2   (TROWS * TPITCH)
#define GATHER_SMEM ((TILE_F2 + LUTN) * (int)sizeof(float2))

// Scratch (device globals: allocation-free per harness rules)
__device__ float2 g_F2T[B_ * G * IMN];               // pass1 out [b][k2][n1]
__device__ __align__(16) float2 g_KGT[B_ * G * G];   // k-grid    [b][k2][k1]
__device__ float4 g_sorted[NBIN * CAP];              // binned points (32 MB)
__device__ int    g_cnt[NBIN];                       // cursor -> final count
__device__ float2 g_tw[512];                         // exp(-i pi pos/half) at [half+pos]
__device__ float  g_apod[IMN];
__device__ float2 g_kblut[LUTN];                     // (value, slope) per (q, tap)

__device__ __forceinline__ float beta_f() {
    return (float)(3.141592653589793 * sqrt(19.45));  // Beatty beta, OS=2, J=6
}

// Abramowitz & Stegun I0 (rel err ~2e-7) — init-time only
__device__ __forceinline__ float bessi0f(float z) {
    if (z < 3.75f) {
        float t = z * z * (1.0f / 14.0625f);
        return 1.0f + t * (3.5156229f + t * (3.0899424f + t * (1.2067492f +
                     t * (0.2659732f + t * (0.0360768f + t * 0.0045813f)))));
    } else {
        float w = 3.75f / z;
        float p = 0.39894228f + w * (0.01328592f + w * (0.00225319f + w * (-0.00157565f +
                  w * (0.00916281f + w * (-0.02057706f + w * (0.02635537f +
                  w * (-0.01647633f + w * 0.00392377f)))))));
        return p * __expf(z) * rsqrtf(z);
    }
}

__device__ __forceinline__ float kb(float u) {
    float x = u * (1.0f / 3.0f);
    float t = 1.0f - x * x;
    if (t <= 0.0f) return 0.0f;
    return bessi0f(beta_f() * sqrtf(t));
}

__device__ __forceinline__ float2 mul_ik(float2 v, int k) {
    switch (k & 3) {
        case 0:  return v;
        case 1:  return make_float2(-v.y,  v.x);
        case 2:  return make_float2(-v.x, -v.y);
        default: return make_float2( v.y, -v.x);
    }
}

// ---------------------------------------------------------------------------
// complex helpers
__device__ __forceinline__ float2 cmul(float2 a, float2 b) {
    return make_float2(a.x * b.x - a.y * b.y, a.x * b.y + a.y * b.x);
}
__device__ __forceinline__ float2 cadd(float2 a, float2 b) { return make_float2(a.x + b.x, a.y + b.y); }
__device__ __forceinline__ float2 csub(float2 a, float2 b) { return make_float2(a.x - b.x, a.y - b.y); }
__device__ __forceinline__ float2 mulmi(float2 a) { return make_float2(a.y, -a.x); }

__device__ __forceinline__ void bf(float2& u, float2& v, float2 w) {
    float2 t = cmul(w, v);
    v = csub(u, t);
    u = cadd(u, t);
}

__device__ __forceinline__ void bfly8(float2* a, float2 wA, float2 wB, float2 wC) {
    const float S = 0.70710678118654752f;
    bf(a[0], a[1], wA); bf(a[2], a[3], wA); bf(a[4], a[5], wA); bf(a[6], a[7], wA);
    float2 wBm = mulmi(wB);
    bf(a[0], a[2], wB);  bf(a[1], a[3], wBm);
    bf(a[4], a[6], wB);  bf(a[5], a[7], wBm);
    float2 wC1 = cmul(wC, make_float2(S, -S));
    float2 wC2 = mulmi(wC);
    float2 wC3 = cmul(wC, make_float2(-S, -S));
    bf(a[0], a[4], wC);  bf(a[1], a[5], wC1);
    bf(a[2], a[6], wC2); bf(a[3], a[7], wC3);
}

__device__ __forceinline__ int swz(int i) { return i ^ (i >> 3); }

// ---------------------------------------------------------------------------
// Init: twiddle table, apod table, KB LUT, zero bin counters.
__global__ void init_kernel() {
    int i = threadIdx.x;          // 512 threads
    if (i >= 1) {
        int half = 1 << (31 - __clz(i));
        int pos  = i - half;
        float ang = -3.14159265358979f * (float)pos / (float)half;
        float s, c;
        __sincosf(ang, &s, &c);
        g_tw[i] = make_float2(c, s);
    } else {
        g_tw[0] = make_float2(1.0f, 0.0f);
    }
    if (i < IMN) {
        float x   = (float)i - 128.0f;
        float arg = (float)(3.141592653589793) * 6.0f * x / 512.0f;
        float bb  = beta_f();
        float t   = bb * bb - arg * arg;
        float st  = sqrtf(t);
        g_apod[i] = st / sinhf(st);
    }
    g_cnt[i] = 0;
    for (int e = i; e < LUTN; e += 512) {
        int q = e / LUTP, j = e - q * LUTP;
        float v = 0.0f, d = 0.0f;
        if (j < J_) {
            float fr  = (float)q * (1.0f / LUTQ);
            float frn = (float)(q + 1) * (1.0f / LUTQ);
            v = kb(fr  - (float)(j - 2));
            d = kb(frn - (float)(j - 2)) - v;
        }
        g_kblut[e] = make_float2(v, d);
    }
}

// rounds 2+3 shared by both passes
__device__ __forceinline__ void fft_rounds23(float2* a, float2* sh, int t) {
    #pragma unroll
    for (int j = 0; j < 8; j++) sh[swz(8 * t + j)] = a[j];
    __syncthreads();
    int base2 = ((t >> 3) << 6) | (t & 7);
    #pragma unroll
    for (int j = 0; j < 8; j++) a[j] = sh[swz(base2 + 8 * j)];
    {
        int d = t & 7;
        bfly8(a, g_tw[8 + d], g_tw[16 + d], g_tw[32 + d]);
    }
    #pragma unroll
    for (int j = 0; j < 8; j++) sh[swz(base2 + 8 * j)] = a[j];
    __syncthreads();
    #pragma unroll
    for (int j = 0; j < 8; j++) a[j] = sh[swz(t + 64 * j)];
    bfly8(a, g_tw[64 + t], g_tw[128 + t], g_tw[256 + t]);
}

__global__ void __launch_bounds__(64) pass1_kernel(const float* __restrict__ img) {
    int b  = blockIdx.x >> 8;
    int n1 = blockIdx.x & 255;
    int t  = threadIdx.x;
    __shared__ float2 sh[512];

    float a1 = g_apod[n1];
    const float* row = img + ((size_t)b * IMN + n1) * IMN;
    int r6 = __brev((unsigned)t) >> 26;

    float2 a[8];
    const int rev3e[4] = {0, 2, 1, 3};
    #pragma unroll
    for (int e = 0; e < 4; e++) {
        int src = (rev3e[e] << 6) | r6;
        float v = row[src] * g_apod[src] * a1;
        a[2 * e]     = make_float2(v, 0.0f);
        a[2 * e + 1] = make_float2(0.0f, 0.0f);
    }
    bfly8(a, make_float2(1.f, 0.f), make_float2(1.f, 0.f), make_float2(1.f, 0.f));
    fft_rounds23(a, sh, t);

    #pragma unroll
    for (int j = 0; j < 8; j++) {
        int k = t + 64 * j;
        g_F2T[((size_t)b * G + k) * IMN + n1] = mul_ik(a[j], k);
    }
}

__global__ void __launch_bounds__(64) pass2_kernel() {
    int b  = blockIdx.x >> 9;
    int k2 = blockIdx.x & 511;
    int t  = threadIdx.x;
    __shared__ float2 sh[512];

    const float2* src = g_F2T + ((size_t)b * G + k2) * IMN;
    int r6 = __brev((unsigned)t) >> 26;

    float2 a[8];
    const int rev3e[4] = {0, 2, 1, 3};
    #pragma unroll
    for (int e = 0; e < 4; e++) {
        int s = (rev3e[e] << 6) | r6;
        a[2 * e]     = src[s];
        a[2 * e + 1] = make_float2(0.0f, 0.0f);
    }
    bfly8(a, make_float2(1.f, 0.f), make_float2(1.f, 0.f), make_float2(1.f, 0.f));
    fft_rounds23(a, sh, t);

    float2* dst = g_KGT + ((size_t)b * G + k2) * G;
    #pragma unroll
    for (int j = 0; j < 8; j++) {
        int k = t + 64 * j;
        dst[k] = mul_ik(a[j], k);
    }
}

// ---------------------------------------------------------------------------
__device__ __forceinline__ int point_bin(int b, float tm1, float tm2) {
    int w1 = ((int)floorf(tm1)) & 511;
    int w2 = ((int)floorf(tm2)) & 511;
    return (b << 6) | ((w2 >> 6) << 3) | (w1 >> 6);
}

__device__ __forceinline__ void load_point(const float* ktraj, int idx,
                                           float& tm1, float& tm2, int& b) {
    b = idx >> 17;
    int m = idx & (M_ - 1);
    const float SC = (float)(512.0 / (2.0 * 3.141592653589793));
    tm1 = ktraj[((size_t)b * 2)     * M_ + m] * SC;
    tm2 = ktraj[((size_t)b * 2 + 1) * M_ + m] * SC;
}

__global__ void __launch_bounds__(HT) scatter_kernel(const float* __restrict__ ktraj,
                                                     const float* __restrict__ dcf) {
    __shared__ int sh[NBIN];
    int tid = threadIdx.x;
    if (tid < NBIN) sh[tid] = 0;
    __syncthreads();

    int start = blockIdx.x * PPB;

    #pragma unroll 4
    for (int k = tid; k < PPB; k += HT) {
        float tm1, tm2; int b;
        load_point(ktraj, start + k, tm1, tm2, b);
        atomicAdd(&sh[point_bin(b, tm1, tm2)], 1);
    }
    __syncthreads();

    if (tid < NBIN) {
        int v = sh[tid];
        sh[tid] = v ? atomicAdd(&g_cnt[tid], v) : 0;
    }
    __syncthreads();

    #pragma unroll 4
    for (int k = tid; k < PPB; k += HT) {
        int idx = start + k;
        float tm1, tm2; int b;
        load_point(ktraj, idx, tm1, tm2, b);
        int m = idx & (M_ - 1);
        float d = dcf[(size_t)b * M_ + m];
        int bin = point_bin(b, tm1, tm2);
        int pos = atomicAdd(&sh[bin], 1);
        if (pos < CAP)
            g_sorted[(size_t)bin * CAP + pos] = make_float4(tm1, tm2, d, __int_as_float(idx));
    }
}

// ---------------------------------------------------------------------------
// Gather: SPLIT blocks per bin; smem tile + smem KB lerp-LUT.
__global__ void __launch_bounds__(256) gather_bin_kernel(float* __restrict__ out) {
    extern __shared__ float2 dyn[];
    float2* tile = dyn;                 // TILE_F2
    float2* klut = dyn + TILE_F2;       // LUTN

    int bin  = blockIdx.x / SPLIT;
    int part = blockIdx.x - bin * SPLIT;
    int b   = bin >> 6;
    int t2  = (bin >> 3) & 7;
    int t1  = bin & 7;
    int tid = threadIdx.x;

    int r0 = t2 * TILE - 2;
    int c0 = t1 * TILE - 2;

    const float2* base = g_KGT + (size_t)b * G * G;
    for (int i = tid; i < TROWS * TROWS; i += 256) {
        int lr = i / TROWS;
        int lc = i - lr * TROWS;
        int gr = (r0 + lr) & 511;
        int gc = (c0 + lc) & 511;
        tile[lr * TPITCH + lc] = base[(size_t)gr * G + gc];
    }
    for (int i = tid; i < LUTN; i += 256) klut[i] = g_kblut[i];
    __syncthreads();

    int cnt = g_cnt[bin];
    if (cnt > CAP) cnt = CAP;
    int chunk = (cnt + SPLIT - 1) / SPLIT;
    int pbeg  = part * chunk;
    int pend  = pbeg + chunk;
    if (pend > cnt) pend = cnt;
    size_t beg = (size_t)bin * CAP;

    for (int p = pbeg + tid; p < pend; p += 256) {
        float4 pt = g_sorted[beg + p];
        float tm1 = pt.x, tm2 = pt.y, d = pt.z;
        int idx = __float_as_int(pt.w);

        float f1 = floorf(tm1), f2 = floorf(tm2);
        float fr1 = tm1 - f1,   fr2 = tm2 - f2;
        int w1 = ((int)f1) & 511;
        int w2 = ((int)f2) & 511;
        int lc = (w1 & 63) + 2;
        int lr = (w2 & 63) + 2;

        float x1 = fr1 * (float)LUTQ;
        float x2 = fr2 * (float)LUTQ;
        int   q1 = (int)x1;  float fc1 = x1 - (float)q1;
        int   q2 = (int)x2;  float fc2 = x2 - (float)q2;
        const float2* l1 = klut + q1 * LUTP;
        const float2* l2 = klut + q2 * LUTP;

        float a1[J_], a2[J_];
        #pragma unroll
        for (int j = 0; j < J_; j++) {
            float2 e1 = l1[j];
            float2 e2 = l2[j];
            a1[j] = fmaf(fc1, e1.y, e1.x);
            a2[j] = fmaf(fc2, e2.y, e2.x);
        }

        float sre = 0.0f, sim = 0.0f;
        const float2* tp = tile + (lr - 2) * TPITCH + (lc - 2);
        #pragma unroll
        for (int j2 = 0; j2 < J_; j2++) {
            const float2* row = tp + j2 * TPITCH;
            float rre = 0.0f, rim = 0.0f;
            #pragma unroll
            for (int j1 = 0; j1 < J_; j1++) {
                float2 v = row[j1];
                rre = fmaf(a1[j1], v.x, rre);
                rim = fmaf(a1[j1], v.y, rim);
            }
            sre = fmaf(a2[j2], rre, sre);
            sim = fmaf(a2[j2], rim, sim);
        }

        out[idx]           = sre * d;
        out[B_ * M_ + idx] = sim * d;
    }
}

// ---------------------------------------------------------------------------
extern "C" void kernel_launch(void* const* d_in, const int* in_sizes, int n_in,
                              void* d_out, int out_size) {
    const float* image = (const float*)d_in[0];   // (8,256,256)
    const float* ktraj = (const float*)d_in[1];   // (8,2,131072)
    const float* dcf   = (const float*)d_in[2];   // (8,131072)
    float* out = (float*)d_out;                   // (2,8,131072)

    cudaFuncSetAttribute(gather_bin_kernel,
                         cudaFuncAttributeMaxDynamicSharedMemorySize, GATHER_SMEM);

    init_kernel      <<<1, 512>>>();
    pass1_kernel     <<<B_ * IMN, 64>>>(image);
    pass2_kernel     <<<B_ * G,   64>>>();
    scatter_kernel   <<<HB, HT>>>(ktraj, dcf);
    gather_bin_kernel<<<NBIN * SPLIT, 256, GATHER_SMEM>>>(out);
}

// round 12
// speedup vs baseline: 1.4968x; 1.2109x over previous
#include <cuda_runtime.h>
#include <cuda_fp16.h>
#include <math.h>

// ---------------------------------------------------------------------------
// NUFFT type-2:  image(8,256,256) -> kdata(2,8,131072)
//   1) de-apodization (table, pre-scaled by 2^11/dim) folded into pass1
//   2) centered zero-pad 512x512 fft2 == FFT512(zero-pad) * i^{k1} * i^{k2}
//      FFT512 = 3 register-resident radix-8 rounds (fp32), 64 thr/row
//   3) k-grid stored as __half2(re,im), values renormalized into fp16 sweet
//      spot (apod * 2^22 total, un-scaled at output); gather taps are 4B LDS
// ---------------------------------------------------------------------------

#define IMN   256
#define G     512
#define B_    8
#define M_    131072            // 2^17
#define NPTS  (B_ * M_)         // 1,048,576
#define J_    6
#define NBIN  512               // 8 batches * 8 * 8 tiles
#define TILE  64
#define TROWS 69                // TILE + 5 halo
#define TPITCH 71               // padded pitch (half2 units)
#define CAP   4096              // per-bin capacity (mean 2048)
#define SPLIT 2                 // gather blocks per bin

#define SCALE_DIM  2048.0f                  // 2^11 per dimension
#define INV_SCALE  (1.0f / 4194304.0f)      // 2^-22 total

#define LUTQ  128               // KB LUT resolution (fr in [0,1))
#define LUTP  9                 // LUT pitch (taps padded 6->9)
#define LUTN  ((LUTQ + 1) * LUTP)

#define HB    512               // scatter blocks
#define HT    512               // scatter threads/block
#define PPB   (NPTS / HB)       // 2048 points per block

#define TILE_H2    (TROWS * TPITCH)
// LUT offset in bytes, aligned up to 16 (TILE_H2*4 = 19596 is NOT 8-aligned)
#define LUT_OFF    ((TILE_H2 * (int)sizeof(__half2) + 15) & ~15)
#define GATHER_SMEM (LUT_OFF + LUTN * (int)sizeof(float2))

// Scratch (device globals: allocation-free per harness rules)
__device__ float2  g_F2T[B_ * G * IMN];              // pass1 out [b][k2][n1], fp32
__device__ __half2 g_KGT[B_ * G * G];                // k-grid half2 [b][k2][k1] (8 MB)
__device__ float4  g_sorted[NBIN * CAP];             // binned points (32 MB)
__device__ int     g_cnt[NBIN];                      // cursor -> final count
__device__ float2  g_tw[512];                        // exp(-i pi pos/half) at [half+pos]
__device__ float   g_apod[IMN];
__device__ float2  g_kblut[LUTN];                    // (value, slope) per (q, tap)

__device__ __forceinline__ float beta_f() {
    return (float)(3.141592653589793 * sqrt(19.45));  // Beatty beta, OS=2, J=6
}

// Abramowitz & Stegun I0 (rel err ~2e-7) — init-time only
__device__ __forceinline__ float bessi0f(float z) {
    if (z < 3.75f) {
        float t = z * z * (1.0f / 14.0625f);
        return 1.0f + t * (3.5156229f + t * (3.0899424f + t * (1.2067492f +
                     t * (0.2659732f + t * (0.0360768f + t * 0.0045813f)))));
    } else {
        float w = 3.75f / z;
        float p = 0.39894228f + w * (0.01328592f + w * (0.00225319f + w * (-0.00157565f +
                  w * (0.00916281f + w * (-0.02057706f + w * (0.02635537f +
                  w * (-0.01647633f + w * 0.00392377f)))))));
        return p * __expf(z) * rsqrtf(z);
    }
}

__device__ __forceinline__ float kb(float u) {
    float x = u * (1.0f / 3.0f);
    float t = 1.0f - x * x;
    if (t <= 0.0f) return 0.0f;
    return bessi0f(beta_f() * sqrtf(t));
}

__device__ __forceinline__ float2 mul_ik(float2 v, int k) {
    switch (k & 3) {
        case 0:  return v;
        case 1:  return make_float2(-v.y,  v.x);
        case 2:  return make_float2(-v.x, -v.y);
        default: return make_float2( v.y, -v.x);
    }
}

// ---------------------------------------------------------------------------
// complex helpers
__device__ __forceinline__ float2 cmul(float2 a, float2 b) {
    return make_float2(a.x * b.x - a.y * b.y, a.x * b.y + a.y * b.x);
}
__device__ __forceinline__ float2 cadd(float2 a, float2 b) { return make_float2(a.x + b.x, a.y + b.y); }
__device__ __forceinline__ float2 csub(float2 a, float2 b) { return make_float2(a.x - b.x, a.y - b.y); }
__device__ __forceinline__ float2 mulmi(float2 a) { return make_float2(a.y, -a.x); }

__device__ __forceinline__ void bf(float2& u, float2& v, float2 w) {
    float2 t = cmul(w, v);
    v = csub(u, t);
    u = cadd(u, t);
}

__device__ __forceinline__ void bfly8(float2* a, float2 wA, float2 wB, float2 wC) {
    const float S = 0.70710678118654752f;
    bf(a[0], a[1], wA); bf(a[2], a[3], wA); bf(a[4], a[5], wA); bf(a[6], a[7], wA);
    float2 wBm = mulmi(wB);
    bf(a[0], a[2], wB);  bf(a[1], a[3], wBm);
    bf(a[4], a[6], wB);  bf(a[5], a[7], wBm);
    float2 wC1 = cmul(wC, make_float2(S, -S));
    float2 wC2 = mulmi(wC);
    float2 wC3 = cmul(wC, make_float2(-S, -S));
    bf(a[0], a[4], wC);  bf(a[1], a[5], wC1);
    bf(a[2], a[6], wC2); bf(a[3], a[7], wC3);
}

__device__ __forceinline__ int swz(int i) { return i ^ (i >> 3); }

// ---------------------------------------------------------------------------
// Init: twiddle table, apod table (pre-scaled), KB LUT, zero bin counters.
__global__ void init_kernel() {
    int i = threadIdx.x;          // 512 threads
    if (i >= 1) {
        int half = 1 << (31 - __clz(i));
        int pos  = i - half;
        float ang = -3.14159265358979f * (float)pos / (float)half;
        float s, c;
        __sincosf(ang, &s, &c);
        g_tw[i] = make_float2(c, s);
    } else {
        g_tw[0] = make_float2(1.0f, 0.0f);
    }
    if (i < IMN) {
        float x   = (float)i - 128.0f;
        float arg = (float)(3.141592653589793) * 6.0f * x / 512.0f;
        float bb  = beta_f();
        float t   = bb * bb - arg * arg;
        float st  = sqrtf(t);
        g_apod[i] = (st / sinhf(st)) * SCALE_DIM;   // 2^11 per dim -> 2^22 total
    }
    g_cnt[i] = 0;
    for (int e = i; e < LUTN; e += 512) {
        int q = e / LUTP, j = e - q * LUTP;
        float v = 0.0f, d = 0.0f;
        if (j < J_) {
            float fr  = (float)q * (1.0f / LUTQ);
            float frn = (float)(q + 1) * (1.0f / LUTQ);
            v = kb(fr  - (float)(j - 2));
            d = kb(frn - (float)(j - 2)) - v;
        }
        g_kblut[e] = make_float2(v, d);
    }
}

// rounds 2+3 shared by both passes
__device__ __forceinline__ void fft_rounds23(float2* a, float2* sh, int t) {
    #pragma unroll
    for (int j = 0; j < 8; j++) sh[swz(8 * t + j)] = a[j];
    __syncthreads();
    int base2 = ((t >> 3) << 6) | (t & 7);
    #pragma unroll
    for (int j = 0; j < 8; j++) a[j] = sh[swz(base2 + 8 * j)];
    {
        int d = t & 7;
        bfly8(a, g_tw[8 + d], g_tw[16 + d], g_tw[32 + d]);
    }
    #pragma unroll
    for (int j = 0; j < 8; j++) sh[swz(base2 + 8 * j)] = a[j];
    __syncthreads();
    #pragma unroll
    for (int j = 0; j < 8; j++) a[j] = sh[swz(t + 64 * j)];
    bfly8(a, g_tw[64 + t], g_tw[128 + t], g_tw[256 + t]);
}

__global__ void __launch_bounds__(64) pass1_kernel(const float* __restrict__ img) {
    int b  = blockIdx.x >> 8;
    int n1 = blockIdx.x & 255;
    int t  = threadIdx.x;
    __shared__ float2 sh[512];

    float a1 = g_apod[n1];
    const float* row = img + ((size_t)b * IMN + n1) * IMN;
    int r6 = __brev((unsigned)t) >> 26;

    float2 a[8];
    const int rev3e[4] = {0, 2, 1, 3};
    #pragma unroll
    for (int e = 0; e < 4; e++) {
        int src = (rev3e[e] << 6) | r6;
        float v = row[src] * g_apod[src] * a1;
        a[2 * e]     = make_float2(v, 0.0f);
        a[2 * e + 1] = make_float2(0.0f, 0.0f);
    }
    bfly8(a, make_float2(1.f, 0.f), make_float2(1.f, 0.f), make_float2(1.f, 0.f));
    fft_rounds23(a, sh, t);

    #pragma unroll
    for (int j = 0; j < 8; j++) {
        int k = t + 64 * j;
        g_F2T[((size_t)b * G + k) * IMN + n1] = mul_ik(a[j], k);
    }
}

__global__ void __launch_bounds__(64) pass2_kernel() {
    int b  = blockIdx.x >> 9;
    int k2 = blockIdx.x & 511;
    int t  = threadIdx.x;
    __shared__ float2 sh[512];

    const float2* src = g_F2T + ((size_t)b * G + k2) * IMN;
    int r6 = __brev((unsigned)t) >> 26;

    float2 a[8];
    const int rev3e[4] = {0, 2, 1, 3};
    #pragma unroll
    for (int e = 0; e < 4; e++) {
        int s = (rev3e[e] << 6) | r6;
        a[2 * e]     = src[s];
        a[2 * e + 1] = make_float2(0.0f, 0.0f);
    }
    bfly8(a, make_float2(1.f, 0.f), make_float2(1.f, 0.f), make_float2(1.f, 0.f));
    fft_rounds23(a, sh, t);

    __half2* dst = g_KGT + ((size_t)b * G + k2) * G;
    #pragma unroll
    for (int j = 0; j < 8; j++) {
        int k = t + 64 * j;
        float2 r = mul_ik(a[j], k);
        dst[k] = __floats2half2_rn(r.x, r.y);    // coalesced 4B store
    }
}

// ---------------------------------------------------------------------------
__device__ __forceinline__ int point_bin(int b, float tm1, float tm2) {
    int w1 = ((int)floorf(tm1)) & 511;
    int w2 = ((int)floorf(tm2)) & 511;
    return (b << 6) | ((w2 >> 6) << 3) | (w1 >> 6);
}

__device__ __forceinline__ void load_point(const float* ktraj, int idx,
                                           float& tm1, float& tm2, int& b) {
    b = idx >> 17;
    int m = idx & (M_ - 1);
    const float SC = (float)(512.0 / (2.0 * 3.141592653589793));
    tm1 = ktraj[((size_t)b * 2)     * M_ + m] * SC;
    tm2 = ktraj[((size_t)b * 2 + 1) * M_ + m] * SC;
}

__global__ void __launch_bounds__(HT) scatter_kernel(const float* __restrict__ ktraj,
                                                     const float* __restrict__ dcf) {
    __shared__ int sh[NBIN];
    int tid = threadIdx.x;
    if (tid < NBIN) sh[tid] = 0;
    __syncthreads();

    int start = blockIdx.x * PPB;

    #pragma unroll 4
    for (int k = tid; k < PPB; k += HT) {
        float tm1, tm2; int b;
        load_point(ktraj, start + k, tm1, tm2, b);
        atomicAdd(&sh[point_bin(b, tm1, tm2)], 1);
    }
    __syncthreads();

    if (tid < NBIN) {
        int v = sh[tid];
        sh[tid] = v ? atomicAdd(&g_cnt[tid], v) : 0;
    }
    __syncthreads();

    #pragma unroll 4
    for (int k = tid; k < PPB; k += HT) {
        int idx = start + k;
        float tm1, tm2; int b;
        load_point(ktraj, idx, tm1, tm2, b);
        int m = idx & (M_ - 1);
        float d = dcf[(size_t)b * M_ + m];
        int bin = point_bin(b, tm1, tm2);
        int pos = atomicAdd(&sh[bin], 1);
        if (pos < CAP)
            g_sorted[(size_t)bin * CAP + pos] = make_float4(tm1, tm2, d, __int_as_float(idx));
    }
}

// ---------------------------------------------------------------------------
// Gather: SPLIT blocks per bin; half2 smem tile (4B taps) + KB lerp-LUT.
__global__ void __launch_bounds__(256) gather_bin_kernel(float* __restrict__ out) {
    extern __shared__ char dyn[];
    __half2* tile = (__half2*)dyn;                 // TILE_H2 half2
    float2*  klut = (float2*)(dyn + LUT_OFF);      // LUTN float2, 16B-aligned

    int bin  = blockIdx.x / SPLIT;
    int part = blockIdx.x - bin * SPLIT;
    int b   = bin >> 6;
    int t2  = (bin >> 3) & 7;
    int t1  = bin & 7;
    int tid = threadIdx.x;

    int r0 = t2 * TILE - 2;
    int c0 = t1 * TILE - 2;

    const __half2* base = g_KGT + (size_t)b * G * G;
    for (int i = tid; i < TROWS * TROWS; i += 256) {
        int lr = i / TROWS;
        int lc = i - lr * TROWS;
        int gr = (r0 + lr) & 511;
        int gc = (c0 + lc) & 511;
        tile[lr * TPITCH + lc] = base[(size_t)gr * G + gc];
    }
    for (int i = tid; i < LUTN; i += 256) klut[i] = g_kblut[i];
    __syncthreads();

    int cnt = g_cnt[bin];
    if (cnt > CAP) cnt = CAP;
    int chunk = (cnt + SPLIT - 1) / SPLIT;
    int pbeg  = part * chunk;
    int pend  = pbeg + chunk;
    if (pend > cnt) pend = cnt;
    size_t beg = (size_t)bin * CAP;

    for (int p = pbeg + tid; p < pend; p += 256) {
        float4 pt = g_sorted[beg + p];
        float tm1 = pt.x, tm2 = pt.y;
        float d = pt.z * INV_SCALE;              // undo 2^22 renormalization
        int idx = __float_as_int(pt.w);

        float f1 = floorf(tm1), f2 = floorf(tm2);
        float fr1 = tm1 - f1,   fr2 = tm2 - f2;
        int w1 = ((int)f1) & 511;
        int w2 = ((int)f2) & 511;
        int lc = (w1 & 63) + 2;
        int lr = (w2 & 63) + 2;

        float x1 = fr1 * (float)LUTQ;
        float x2 = fr2 * (float)LUTQ;
        int   q1 = (int)x1;  float fc1 = x1 - (float)q1;
        int   q2 = (int)x2;  float fc2 = x2 - (float)q2;
        const float2* l1 = klut + q1 * LUTP;
        const float2* l2 = klut + q2 * LUTP;

        float a1[J_], a2[J_];
        #pragma unroll
        for (int j = 0; j < J_; j++) {
            float2 e1 = l1[j];
            float2 e2 = l2[j];
            a1[j] = fmaf(fc1, e1.y, e1.x);
            a2[j] = fmaf(fc2, e2.y, e2.x);
        }

        float sre = 0.0f, sim = 0.0f;
        const __half2* tp = tile + (lr - 2) * TPITCH + (lc - 2);
        #pragma unroll
        for (int j2 = 0; j2 < J_; j2++) {
            const __half2* row = tp + j2 * TPITCH;
            float rre = 0.0f, rim = 0.0f;
            #pragma unroll
            for (int j1 = 0; j1 < J_; j1++) {
                float2 v = __half22float2(row[j1]);
                rre = fmaf(a1[j1], v.x, rre);
                rim = fmaf(a1[j1], v.y, rim);
            }
            sre = fmaf(a2[j2], rre, sre);
            sim = fmaf(a2[j2], rim, sim);
        }

        out[idx]           = sre * d;
        out[B_ * M_ + idx] = sim * d;
    }
}

// ---------------------------------------------------------------------------
extern "C" void kernel_launch(void* const* d_in, const int* in_sizes, int n_in,
                              void* d_out, int out_size) {
    const float* image = (const float*)d_in[0];   // (8,256,256)
    const float* ktraj = (const float*)d_in[1];   // (8,2,131072)
    const float* dcf   = (const float*)d_in[2];   // (8,131072)
    float* out = (float*)d_out;                   // (2,8,131072)

    cudaFuncSetAttribute(gather_bin_kernel,
                         cudaFuncAttributeMaxDynamicSharedMemorySize, GATHER_SMEM);

    init_kernel      <<<1, 512>>>();
    pass1_kernel     <<<B_ * IMN, 64>>>(image);
    pass2_kernel     <<<B_ * G,   64>>>();
    scatter_kernel   <<<HB, HT>>>(ktraj, dcf);
    gather_bin_kernel<<<NBIN * SPLIT, 256, GATHER_SMEM>>>(out);
}